// round 2
// baseline (speedup 1.0000x reference)
#include <cuda_runtime.h>
#include <math.h>

#define SPB       16            // sequences per block
#define T_LEN     34
#define NTAB      340           // 34 positions x 10 vocab
#define BTHREADS  (SPB * T_LEN) // 544

// flat[t] = _OFFS[_SRC[t]] + _IDX[t]  (precomputed on host side of the math)
__constant__ int c_flat[T_LEN] = {
    0,1,2,3,4,5,6,7,8,9, 11,
    0,1,2,3,4,5,6,7,8,9, 12,
    0,1,2,3,4,5,6,7,8,9, 10, 13
};

__global__ __launch_bounds__(BTHREADS)
void micro_fused_kernel(
    const int*   __restrict__ idx,        // (B,34)
    const float* __restrict__ tokA,       // (1,)
    const float* __restrict__ tokStart,   // (1,)
    const float* __restrict__ tokStride,  // (1,)
    const float* __restrict__ z_hi,       // (1,3)
    const float* __restrict__ specialEq,  // (1,3)
    const float* __restrict__ qW,         // (4,3)
    const float* __restrict__ phase,      // (1,)
    const float* __restrict__ outA,       // (5,1)
    const float* __restrict__ outB,       // (1,5)
    const float* __restrict__ nw,         // (5,)
    const float* __restrict__ fc1,        // (2,5)
    const float* __restrict__ hp,         // (2,5)  head_proj_w
    float*       __restrict__ out,        // (B,34,10)
    int B)
{
    __shared__ float4 s_q [NTAB];   // rotated q, per (t, digit)
    __shared__ float4 s_k [NTAB];   // unrotated q * 0.5 (scale baked in)
    __shared__ float4 s_v4[NTAB];   // v[0..3]
    __shared__ float  s_v1[NTAB];   // v[4]
    __shared__ float4 s_x4[NTAB];   // pre-norm x[0..3]
    __shared__ float  s_x1[NTAB];   // x[4]
    __shared__ int    s_j [SPB][T_LEN];   // s*10 + token
    __shared__ float  s_tt0[10], s_tt1[10];   // tok_table columns
    __shared__ float  s_cA[5], s_cB[5], s_w[5], s_fc1[10], s_hp[10];

    const int tid = threadIdx.x;

    // ---- coalesced idx load: one int per thread, linear ----
    {
        long g = (long)blockIdx.x * (SPB * T_LEN) + tid;
        if (g < (long)B * T_LEN) {
            int yy = tid / T_LEN;
            int ss = tid - yy * T_LEN;
            s_j[yy][ss] = ss * 10 + idx[g];
        }
    }
    if (tid < 5)  { s_cA[tid] = outA[tid]; s_cB[tid] = outB[tid]; s_w[tid] = nw[tid]; }
    if (tid < 10) { s_fc1[tid] = fc1[tid]; s_hp[tid] = hp[tid]; }

    // ---- build per-(position,digit) tables in smem ----
    if (tid < NTAB) {
        const int tpos = tid / 10;
        const int c    = tid - tpos * 10;
        const int f    = c_flat[tpos];

        float p0, p1, p2;
        if (f < 10) {
            float a = 0.6283185307179586f * (float)f;   // 2*pi/10 * f
            p0 = 3.5f * cosf(a);
            p1 = 3.5f * sinf(a);
            p2 = 0.15f * (float)f;
        } else if (f == 10) {
            p0 = z_hi[0]; p1 = z_hi[1]; p2 = z_hi[2];
        } else if (f == 12) {
            p0 = specialEq[0]; p1 = specialEq[1]; p2 = specialEq[2];
        } else {
            p0 = p1 = p2 = 0.0f;
        }

        float ang = tokStart[0] + (float)c * tokStride[0];
        float amp = tokA[0];
        float x0 = amp * cosf(ang);
        float x1 = amp * sinf(ang);

        s_x4[tid] = make_float4(x0, x1, p0, p1);
        s_x1[tid] = p2;
        if (tpos == 0) { s_tt0[c] = x0; s_tt1[c] = x1; }   // tok_table rows

        float ms = 0.2f * (x0*x0 + x1*x1 + p0*p0 + p1*p1 + p2*p2);
        float r  = rsqrtf(ms + 1e-5f);
        float h0 = x0 * r * nw[0];
        float h1 = x1 * r * nw[1];
        float h2 = p0 * r * nw[2];
        float h3 = p1 * r * nw[3];
        float h4 = p2 * r * nw[4];

        float q0 = qW[0]*h2 + qW[1]*h3 + qW[2]*h4;
        float q1 = qW[3]*h2 + qW[4]*h3 + qW[5]*h4;
        float q2 = qW[6]*h2 + qW[7]*h3 + qW[8]*h4;
        float q3 = qW[9]*h2 + qW[10]*h3 + qW[11]*h4;

        s_k[tid] = make_float4(0.5f*q0, 0.5f*q1, 0.5f*q2, 0.5f*q3);  // /sqrt(4) baked

        float cp = cosf(phase[0]);
        float sp = sinf(phase[0]);
        s_q[tid] = make_float4(q0*cp - q1*sp, q0*sp + q1*cp,
                               q2*cp - q3*sp, q2*sp + q3*cp);

        s_v4[tid] = make_float4(h0*hp[0] + h1*hp[5],
                                h0*hp[1] + h1*hp[6],
                                h0*hp[2] + h1*hp[7],
                                h0*hp[3] + h1*hp[8]);
        s_v1[tid] = h0*hp[4] + h1*hp[9];
    }
    __syncthreads();

    // ---- per-(sequence, position) attention + epilogue ----
    const int y = tid & (SPB - 1);   // sequence within block (lanes: 16 seqs x 2 t-values)
    const int t = tid >> 4;          // position 0..33
    const long seq = (long)blockIdx.x * SPB + y;
    if (seq >= B) return;

    const int jt = s_j[y][t];
    const float4 q = s_q[jt];
    const int* __restrict__ jrow = s_j[y];

    float a0 = 0.f, a1 = 0.f, a2 = 0.f, a3 = 0.f, a4 = 0.f, den = 0.f;

    #pragma unroll 4
    for (int s = 0; s <= t; ++s) {
        const int j = jrow[s];
        const float4 k = s_k[j];
        float d = fmaf(q.x, k.x, fmaf(q.y, k.y, fmaf(q.z, k.z, q.w * k.w)));
        float e = __expf(d);
        den += e;
        const float4 v = s_v4[j];
        a0 = fmaf(e, v.x, a0);
        a1 = fmaf(e, v.y, a1);
        a2 = fmaf(e, v.z, a2);
        a3 = fmaf(e, v.w, a3);
        a4 = fmaf(e, s_v1[j], a4);
    }

    const float rn = 1.0f / den;
    const float o0 = a0*rn, o1 = a1*rn, o2 = a2*rn, o3 = a3*rn, o4 = a4*rn;

    // x1 = x + (o . A) * B   (rank-1 out_proj)
    const float dA = o0*s_cA[0] + o1*s_cA[1] + o2*s_cA[2] + o3*s_cA[3] + o4*s_cA[4];
    const float4 xv = s_x4[jt];
    const float  x4v = s_x1[jt];
    float X0 = xv.x + dA*s_cB[0];
    float X1 = xv.y + dA*s_cB[1];
    float X2 = xv.z + dA*s_cB[2];
    float X3 = xv.w + dA*s_cB[3];
    float X4 = x4v  + dA*s_cB[4];

    // FFN: rmsnorm -> fc1 -> exact gelu -> head_proj, residual
    float ms1 = 0.2f*(X0*X0 + X1*X1 + X2*X2 + X3*X3 + X4*X4);
    float r1  = rsqrtf(ms1 + 1e-5f);
    float H0 = X0*r1*s_w[0], H1 = X1*r1*s_w[1], H2 = X2*r1*s_w[2],
          H3 = X3*r1*s_w[3], H4 = X4*r1*s_w[4];
    float z0 = H0*s_fc1[0] + H1*s_fc1[1] + H2*s_fc1[2] + H3*s_fc1[3] + H4*s_fc1[4];
    float z1 = H0*s_fc1[5] + H1*s_fc1[6] + H2*s_fc1[7] + H3*s_fc1[8] + H4*s_fc1[9];
    float g0 = 0.5f*z0*(1.0f + erff(z0 * 0.70710678118654752f));
    float g1 = 0.5f*z1*(1.0f + erff(z1 * 0.70710678118654752f));
    float Y0 = X0 + g0*s_hp[0] + g1*s_hp[5];
    float Y1 = X1 + g0*s_hp[1] + g1*s_hp[6];
    float Y2 = X2 + g0*s_hp[2] + g1*s_hp[7];
    float Y3 = X3 + g0*s_hp[3] + g1*s_hp[8];
    float Y4 = X4 + g0*s_hp[4] + g1*s_hp[9];

    // final: rmsnorm -> head_proj_w.T (5->2) -> tok_table.T (2->10)
    float ms2 = 0.2f*(Y0*Y0 + Y1*Y1 + Y2*Y2 + Y3*Y3 + Y4*Y4);
    float r2  = rsqrtf(ms2 + 1e-5f);
    float G0 = Y0*r2*s_w[0], G1 = Y1*r2*s_w[1], G2 = Y2*r2*s_w[2],
          G3 = Y3*r2*s_w[3], G4 = Y4*r2*s_w[4];
    float u0 = G0*s_hp[0] + G1*s_hp[1] + G2*s_hp[2] + G3*s_hp[3] + G4*s_hp[4];
    float u1 = G0*s_hp[5] + G1*s_hp[6] + G2*s_hp[7] + G3*s_hp[8] + G4*s_hp[9];

    float* op = out + (size_t)seq * (T_LEN * 10) + t * 10;
    #pragma unroll
    for (int d = 0; d < 10; d += 2) {
        float2 w2 = make_float2(u0*s_tt0[d]   + u1*s_tt1[d],
                                u0*s_tt0[d+1] + u1*s_tt1[d+1]);
        *(float2*)(op + d) = w2;   // 8B-aligned: 340*4 and 40 are both mult of 8
    }
}

extern "C" void kernel_launch(void* const* d_in, const int* in_sizes, int n_in,
                              void* d_out, int out_size)
{
    const int B = in_sizes[0] / T_LEN;
    const int grid = (B + SPB - 1) / SPB;
    micro_fused_kernel<<<grid, BTHREADS>>>(
        (const int*)d_in[0],
        (const float*)d_in[1],
        (const float*)d_in[2],
        (const float*)d_in[3],
        (const float*)d_in[4],
        (const float*)d_in[5],
        (const float*)d_in[6],
        (const float*)d_in[7],
        (const float*)d_in[8],
        (const float*)d_in[9],
        (const float*)d_in[10],
        (const float*)d_in[11],
        (const float*)d_in[12],
        (float*)d_out, B);
}

// round 3
// speedup vs baseline: 1.8608x; 1.8608x over previous
#include <cuda_runtime.h>
#include <math.h>

#define SPB       32            // sequences per block
#define T_LEN     34
#define NTAB      340           // 34 positions x 10 vocab
#define NG        17            // t-groups of 2 -> warp per group
#define BTHREADS  (SPB * NG)    // 544
#define JSTRIDE   35            // padded row stride for s_j (conflict-free: 3y+s distinct mod 32)

// flat[t] = _OFFS[_SRC[t]] + _IDX[t]
__constant__ int c_flat[T_LEN] = {
    0,1,2,3,4,5,6,7,8,9, 11,
    0,1,2,3,4,5,6,7,8,9, 12,
    0,1,2,3,4,5,6,7,8,9, 10, 13
};

__global__ __launch_bounds__(BTHREADS, 2)
void micro_fused2(
    const int*   __restrict__ idx,        // (B,34)
    const float* __restrict__ tokA,
    const float* __restrict__ tokStart,
    const float* __restrict__ tokStride,
    const float* __restrict__ z_hi,       // (3,)
    const float* __restrict__ specialEq,  // (3,)
    const float* __restrict__ qW,         // (4,3)
    const float* __restrict__ phase,      // (1,)
    const float* __restrict__ outA,       // (5,)
    const float* __restrict__ outB,       // (5,)
    const float* __restrict__ nw,         // (5,)
    const float* __restrict__ fc1,        // (2,5)
    const float* __restrict__ hp,         // (2,5)
    float*       __restrict__ out,        // (B,34,10)
    int B)
{
    __shared__ float4 s_tab[NTAB];            // p0,p1,p2, v' (score key + collapsed value)
    __shared__ float4 s_m  [NTAB];            // m0,m1,m2 (M^T p), .w = x4 (pre-norm 5th comp)
    __shared__ float4 s_x4 [NTAB];            // pre-norm x[0..3]
    __shared__ int    s_j  [SPB * JSTRIDE];   // s*10 + token
    __shared__ float2 s_u  [SPB * T_LEN + 1]; // (u0,u1) staging (+1 pad for tail reload)
    __shared__ float  s_tt0[10], s_tt1[10];   // tok_table columns
    __shared__ float  s_cB[5], s_w[5], s_fc1[10], s_hp[10];

    const int  tid       = threadIdx.x;
    const long base_tok  = (long)blockIdx.x * (SPB * T_LEN);
    const long total_tok = (long)B * T_LEN;

    // ---- coalesced idx load: 2 ints per thread ----
    #pragma unroll
    for (int r = 0; r < 2; ++r) {
        int  li = tid + r * BTHREADS;          // 0..1087
        int  yy = li / T_LEN;
        int  ss = li - yy * T_LEN;
        long g  = base_tok + li;
        int  v  = (g < total_tok) ? idx[g] : 0;
        s_j[yy * JSTRIDE + ss] = ss * 10 + v;
    }
    if (tid < 5)  { s_cB[tid] = outB[tid]; s_w[tid] = nw[tid]; }
    if (tid < 10) { s_fc1[tid] = fc1[tid]; s_hp[tid] = hp[tid]; }

    // ---- build 340-entry tables (reads params from global only: no smem race) ----
    if (tid < NTAB) {
        const int tpos = tid / 10;
        const int c    = tid - tpos * 10;
        const int f    = c_flat[tpos];

        float p0, p1, p2;
        if (f < 10) {
            float a = 0.6283185307179586f * (float)f;
            p0 = 3.5f * cosf(a);
            p1 = 3.5f * sinf(a);
            p2 = 0.15f * (float)f;
        } else if (f == 10) {
            p0 = z_hi[0]; p1 = z_hi[1]; p2 = z_hi[2];
        } else if (f == 12) {
            p0 = specialEq[0]; p1 = specialEq[1]; p2 = specialEq[2];
        } else {
            p0 = p1 = p2 = 0.0f;
        }

        float ang = tokStart[0] + (float)c * tokStride[0];
        float amp = tokA[0];
        float x0 = amp * cosf(ang);
        float x1 = amp * sinf(ang);

        s_x4[tid] = make_float4(x0, x1, p0, p1);
        if (tpos == 0) { s_tt0[c] = x0; s_tt1[c] = x1; }

        float ms = 0.2f * (x0*x0 + x1*x1 + p0*p0 + p1*p1 + p2*p2);
        float r  = rsqrtf(ms + 1e-5f);
        float h0 = x0 * r * nw[0];
        float h1 = x1 * r * nw[1];
        float h2 = p0 * r * nw[2];
        float h3 = p1 * r * nw[3];
        float h4 = p2 * r * nw[4];

        // q = qW @ (h2,h3,h4)
        float q0 = qW[0]*h2 + qW[1]*h3 + qW[2]*h4;
        float q1 = qW[3]*h2 + qW[4]*h3 + qW[5]*h4;
        float q2 = qW[6]*h2 + qW[7]*h3 + qW[8]*h4;
        float q3 = qW[9]*h2 + qW[10]*h3 + qW[11]*h4;

        // m = 0.5 * qW^T R^T (rotated q): d(t,s) = m_t . p_s
        float cp = cosf(phase[0]);
        float sp = sinf(phase[0]);
        float r0 = q0*cp - q1*sp;
        float r1v = q0*sp + q1*cp;
        float r2v = q2*cp - q3*sp;
        float r3 = q2*sp + q3*cp;
        float m0 = 0.5f*(r0*qW[0] + r1v*qW[3] + r2v*qW[6] + r3*qW[9]);
        float m1 = 0.5f*(r0*qW[1] + r1v*qW[4] + r2v*qW[7] + r3*qW[10]);
        float m2 = 0.5f*(r0*qW[2] + r1v*qW[5] + r2v*qW[8] + r3*qW[11]);

        // collapsed value scalar: v' = h0*(hp_row0 . outA) + h1*(hp_row1 . outA)
        float w0s = hp[0]*outA[0] + hp[1]*outA[1] + hp[2]*outA[2] + hp[3]*outA[3] + hp[4]*outA[4];
        float w1s = hp[5]*outA[0] + hp[6]*outA[1] + hp[7]*outA[2] + hp[8]*outA[3] + hp[9]*outA[4];
        float vp  = h0*w0s + h1*w1s;

        s_tab[tid] = make_float4(h2, h3, h4, vp);
        s_m[tid]   = make_float4(m0, m1, m2, p2);  // .w = pre-norm x[4]
    }
    __syncthreads();

    // ---- attention: warp = one t-group (t0,t1), lanes = 32 sequences ----
    const int y  = tid & 31;
    const int gr = tid >> 5;            // 0..16
    const int t0 = gr * 2, t1 = t0 + 1;
    const int* __restrict__ jrow = s_j + y * JSTRIDE;

    const int jt0 = jrow[t0];
    const int jt1 = jrow[t1];
    const float4 ma = s_m[jt0];
    const float4 mb = s_m[jt1];

    float dena = 0.f, bacc = 0.f, denb = 0.f, bbcc = 0.f;

    #pragma unroll 2
    for (int s = 0; s <= t0; ++s) {
        const int j = jrow[s];
        const float4 kp = s_tab[j];
        float da = fmaf(ma.x, kp.x, fmaf(ma.y, kp.y, ma.z * kp.z));
        float db = fmaf(mb.x, kp.x, fmaf(mb.y, kp.y, mb.z * kp.z));
        float ea = __expf(da);
        float eb = __expf(db);
        dena += ea;  bacc = fmaf(ea, kp.w, bacc);
        denb += eb;  bbcc = fmaf(eb, kp.w, bbcc);
    }
    {   // s = t1: contributes to t1 only
        const float4 kp = s_tab[jt1];
        float db = fmaf(mb.x, kp.x, fmaf(mb.y, kp.y, mb.z * kp.z));
        float eb = __expf(db);
        denb += eb;  bbcc = fmaf(eb, kp.w, bbcc);
    }

    // ---- epilogue (twice: t0 and t1) ----
    #pragma unroll
    for (int which = 0; which < 2; ++which) {
        const int   t   = which ? t1 : t0;
        const int   jt  = which ? jt1 : jt0;
        const float den = which ? denb : dena;
        const float bb  = which ? bbcc : bacc;

        const float dA = bb * __fdividef(1.0f, den);

        const float4 xv  = s_x4[jt];
        const float  x4v = s_m[jt].w;
        float X0 = fmaf(dA, s_cB[0], xv.x);
        float X1 = fmaf(dA, s_cB[1], xv.y);
        float X2 = fmaf(dA, s_cB[2], xv.z);
        float X3 = fmaf(dA, s_cB[3], xv.w);
        float X4 = fmaf(dA, s_cB[4], x4v);

        float ms1 = 0.2f*(X0*X0 + X1*X1 + X2*X2 + X3*X3 + X4*X4);
        float r1  = rsqrtf(ms1 + 1e-5f);
        float H0 = X0*r1*s_w[0], H1 = X1*r1*s_w[1], H2 = X2*r1*s_w[2],
              H3 = X3*r1*s_w[3], H4 = X4*r1*s_w[4];
        float z0 = H0*s_fc1[0] + H1*s_fc1[1] + H2*s_fc1[2] + H3*s_fc1[3] + H4*s_fc1[4];
        float z1 = H0*s_fc1[5] + H1*s_fc1[6] + H2*s_fc1[7] + H3*s_fc1[8] + H4*s_fc1[9];
        float g0 = 0.5f*z0*(1.0f + erff(z0 * 0.70710678118654752f));
        float g1 = 0.5f*z1*(1.0f + erff(z1 * 0.70710678118654752f));
        float Y0 = X0 + g0*s_hp[0] + g1*s_hp[5];
        float Y1 = X1 + g0*s_hp[1] + g1*s_hp[6];
        float Y2 = X2 + g0*s_hp[2] + g1*s_hp[7];
        float Y3 = X3 + g0*s_hp[3] + g1*s_hp[8];
        float Y4 = X4 + g0*s_hp[4] + g1*s_hp[9];

        float ms2 = 0.2f*(Y0*Y0 + Y1*Y1 + Y2*Y2 + Y3*Y3 + Y4*Y4);
        float r2  = rsqrtf(ms2 + 1e-5f);
        float G0 = Y0*r2*s_w[0], G1 = Y1*r2*s_w[1], G2 = Y2*r2*s_w[2],
              G3 = Y3*r2*s_w[3], G4 = Y4*r2*s_w[4];
        float u0 = G0*s_hp[0] + G1*s_hp[1] + G2*s_hp[2] + G3*s_hp[3] + G4*s_hp[4];
        float u1 = G0*s_hp[5] + G1*s_hp[6] + G2*s_hp[7] + G3*s_hp[8] + G4*s_hp[9];

        s_u[y * T_LEN + t] = make_float2(u0, u1);
    }
    __syncthreads();

    // ---- staged, fully coalesced float4 output: block region = 43520B contiguous ----
    const long base_f  = base_tok * 10;
    const long total_f = total_tok * 10;
    float* __restrict__ ob = out + base_f;

    #pragma unroll
    for (int r = 0; r < 5; ++r) {
        const int f4 = tid + r * BTHREADS;       // 0..2719
        const int el = f4 * 4;
        if (base_f + el + 4 <= total_f) {
            int tq = el / 10;                    // = y*34 + t
            int d  = el - tq * 10;
            float2 u = s_u[tq];
            float vv[4];
            #pragma unroll
            for (int k2 = 0; k2 < 4; ++k2) {
                vv[k2] = fmaf(u.y, s_tt1[d], u.x * s_tt0[d]);
                if (++d == 10) { d = 0; ++tq; u = s_u[tq]; }
            }
            reinterpret_cast<float4*>(ob)[f4] = make_float4(vv[0], vv[1], vv[2], vv[3]);
        }
    }
}

extern "C" void kernel_launch(void* const* d_in, const int* in_sizes, int n_in,
                              void* d_out, int out_size)
{
    const int B = in_sizes[0] / T_LEN;
    const int grid = (B + SPB - 1) / SPB;
    micro_fused2<<<grid, BTHREADS>>>(
        (const int*)d_in[0],
        (const float*)d_in[1],
        (const float*)d_in[2],
        (const float*)d_in[3],
        (const float*)d_in[4],
        (const float*)d_in[5],
        (const float*)d_in[6],
        (const float*)d_in[7],
        (const float*)d_in[8],
        (const float*)d_in[9],
        (const float*)d_in[10],
        (const float*)d_in[11],
        (const float*)d_in[12],
        (float*)d_out, B);
}

// round 4
// speedup vs baseline: 2.1115x; 1.1348x over previous
#include <cuda_runtime.h>
#include <math.h>

#define SPB       32
#define T_LEN     34
#define NTAB      340
#define NWARP     9
#define BTHREADS  288
#define JSTRIDE   35           // padded int stride, conflict-free scalar LDS

// flat[t] = _OFFS[_SRC[t]] + _IDX[t]
__constant__ int c_flat[T_LEN] = {
    0,1,2,3,4,5,6,7,8,9, 11,
    0,1,2,3,4,5,6,7,8,9, 12,
    0,1,2,3,4,5,6,7,8,9, 10, 13
};

__device__ __forceinline__ float ex2f(float x) {
    float y;
    asm("ex2.approx.ftz.f32 %0, %1;" : "=f"(y) : "f"(x));
    return y;
}

__global__ __launch_bounds__(BTHREADS, 3)
void micro_fused3(
    const int*   __restrict__ idx,        // (B,34)
    const float* __restrict__ tokA,
    const float* __restrict__ tokStart,
    const float* __restrict__ tokStride,
    const float* __restrict__ z_hi,       // (3,)
    const float* __restrict__ specialEq,  // (3,)
    const float* __restrict__ qW,         // (4,3)
    const float* __restrict__ phase,      // (1,)
    const float* __restrict__ outA,       // (5,)
    const float* __restrict__ outB,       // (5,)
    const float* __restrict__ nw,         // (5,)
    const float* __restrict__ fc1,        // (2,5)
    const float* __restrict__ hp,         // (2,5)
    float*       __restrict__ out,        // (B,34,10)
    int B)
{
    __shared__ float4 s_tab[NTAB];            // p0,p1,p2 (score key), v' (collapsed value)
    __shared__ float4 s_m  [NTAB];            // log2e * M^T p (3), .w = pre-norm x4
    __shared__ float4 s_x4 [NTAB];            // pre-norm x[0..3]
    __shared__ int    s_j  [SPB * JSTRIDE];   // BYTE offset: (s*10+c)*16
    __shared__ float2 s_u  [SPB * T_LEN + 1];
    __shared__ float  s_tt0[10], s_tt1[10];
    __shared__ float  s_cB[5], s_hp[10], s_wf[10], s_wh[10];

    const int  tid       = threadIdx.x;
    const long base_tok  = (long)blockIdx.x * (SPB * T_LEN);
    const long total_tok = (long)B * T_LEN;

    // ---- coalesced idx load ----
    #pragma unroll
    for (int r = 0; r < 4; ++r) {
        int li = tid + r * BTHREADS;            // 0..1151
        if (li < SPB * T_LEN) {
            int  yy = li / T_LEN;
            int  ss = li - yy * T_LEN;
            long g  = base_tok + li;
            int  v  = (g < total_tok) ? idx[g] : 0;
            s_j[yy * JSTRIDE + ss] = (ss * 10 + v) << 4;   // byte offset into float4 tables
        }
    }
    if (tid < 5)  s_cB[tid] = outB[tid];
    if (tid < 10) {
        s_hp[tid] = hp[tid];
        int cc = tid % 5;
        s_wf[tid] = nw[cc] * fc1[tid];   // folded rmsnorm weight * fc1
        s_wh[tid] = nw[cc] * hp[tid];    // folded rmsnorm weight * head_proj
    }

    // ---- build 340-entry tables ----
    for (int i = tid; i < NTAB; i += BTHREADS) {
        const int tpos = i / 10;
        const int c    = i - tpos * 10;
        const int f    = c_flat[tpos];

        float p0, p1, p2;
        if (f < 10) {
            float a = 0.6283185307179586f * (float)f;
            p0 = 3.5f * cosf(a);
            p1 = 3.5f * sinf(a);
            p2 = 0.15f * (float)f;
        } else if (f == 10) {
            p0 = z_hi[0]; p1 = z_hi[1]; p2 = z_hi[2];
        } else if (f == 12) {
            p0 = specialEq[0]; p1 = specialEq[1]; p2 = specialEq[2];
        } else {
            p0 = p1 = p2 = 0.0f;
        }

        float ang = tokStart[0] + (float)c * tokStride[0];
        float amp = tokA[0];
        float x0 = amp * cosf(ang);
        float x1 = amp * sinf(ang);

        s_x4[i] = make_float4(x0, x1, p0, p1);
        if (tpos == 0) { s_tt0[c] = x0; s_tt1[c] = x1; }

        float ms = 0.2f * (x0*x0 + x1*x1 + p0*p0 + p1*p1 + p2*p2);
        float r  = rsqrtf(ms + 1e-5f);
        float h0 = x0 * r * nw[0];
        float h1 = x1 * r * nw[1];
        float h2 = p0 * r * nw[2];
        float h3 = p1 * r * nw[3];
        float h4 = p2 * r * nw[4];

        float q0 = qW[0]*h2 + qW[1]*h3 + qW[2]*h4;
        float q1 = qW[3]*h2 + qW[4]*h3 + qW[5]*h4;
        float q2 = qW[6]*h2 + qW[7]*h3 + qW[8]*h4;
        float q3 = qW[9]*h2 + qW[10]*h3 + qW[11]*h4;

        float cp = cosf(phase[0]);
        float sp = sinf(phase[0]);
        float r0  = q0*cp - q1*sp;
        float r1v = q0*sp + q1*cp;
        float r2v = q2*cp - q3*sp;
        float r3  = q2*sp + q3*cp;
        // 0.5/sqrt-scale and log2(e) both baked into m
        const float LG = 0.5f * 1.4426950408889634f;
        float m0 = LG*(r0*qW[0] + r1v*qW[3] + r2v*qW[6] + r3*qW[9]);
        float m1 = LG*(r0*qW[1] + r1v*qW[4] + r2v*qW[7] + r3*qW[10]);
        float m2 = LG*(r0*qW[2] + r1v*qW[5] + r2v*qW[8] + r3*qW[11]);

        float w0s = hp[0]*outA[0] + hp[1]*outA[1] + hp[2]*outA[2] + hp[3]*outA[3] + hp[4]*outA[4];
        float w1s = hp[5]*outA[0] + hp[6]*outA[1] + hp[7]*outA[2] + hp[8]*outA[3] + hp[9]*outA[4];
        float vp  = h0*w0s + h1*w1s;

        s_tab[i] = make_float4(h2, h3, h4, vp);
        s_m[i]   = make_float4(m0, m1, m2, p2);
    }
    __syncthreads();

    // ---- attention: warp gr handles t in {gr, 17-gr, 18+gr, 35-gr} ----
    const int y  = tid & 31;
    const int gr = tid >> 5;                 // 0..8
    const int t0 = gr, t1 = 17 - gr, t2 = 18 + gr, t3 = 35 - gr;
    const int t3c = (t3 > 33) ? 33 : t3;

    const int* __restrict__ jrow = s_j + y * JSTRIDE;
    const char* __restrict__ tabb = (const char*)s_tab;
    const char* __restrict__ mbb  = (const char*)s_m;

    const int j0 = jrow[t0], j1 = jrow[t1], j2 = jrow[t2], j3 = jrow[t3c];
    const float4 m0 = *(const float4*)(mbb + j0);
    const float4 m1 = *(const float4*)(mbb + j1);
    const float4 m2 = *(const float4*)(mbb + j2);
    const float4 m3 = *(const float4*)(mbb + j3);

    float den0 = 0.f, b0 = 0.f, den1 = 0.f, b1 = 0.f;
    float den2 = 0.f, b2 = 0.f, den3 = 0.f, b3 = 0.f;

#define STEP(MM, DD, BB)                                                  \
    { float dd = fmaf(MM.x, kp.x, fmaf(MM.y, kp.y, MM.z * kp.z));         \
      float ee = ex2f(dd);                                                \
      DD += ee; BB = fmaf(ee, kp.w, BB); }

    int s = 0;
    #pragma unroll 2
    for (; s <= t0; ++s) {
        const float4 kp = *(const float4*)(tabb + jrow[s]);
        STEP(m0, den0, b0) STEP(m1, den1, b1) STEP(m2, den2, b2) STEP(m3, den3, b3)
    }
    #pragma unroll 2
    for (; s <= t1; ++s) {
        const float4 kp = *(const float4*)(tabb + jrow[s]);
        STEP(m1, den1, b1) STEP(m2, den2, b2) STEP(m3, den3, b3)
    }
    #pragma unroll 2
    for (; s <= t2; ++s) {
        const float4 kp = *(const float4*)(tabb + jrow[s]);
        STEP(m2, den2, b2) STEP(m3, den3, b3)
    }
    #pragma unroll 2
    for (; s <= t3c; ++s) {
        const float4 kp = *(const float4*)(tabb + jrow[s]);
        STEP(m3, den3, b3)
    }
#undef STEP

    // ---- epilogue for the 4 t's ----
    const int   tt[4] = {t0, t1, t2, t3};
    const int   jj[4] = {j0, j1, j2, j3};
    const float dn[4] = {den0, den1, den2, den3};
    const float bb[4] = {b0, b1, b2, b3};

    #pragma unroll
    for (int i = 0; i < 4; ++i) {
        const int t = tt[i];
        if (t <= 33) {
            const float dA = __fdividef(bb[i], dn[i]);

            const float4 xv  = *(const float4*)((const char*)s_x4 + jj[i]);
            const float  x4v = ((const float4*)(mbb + jj[i]))->w;
            float X0 = fmaf(dA, s_cB[0], xv.x);
            float X1 = fmaf(dA, s_cB[1], xv.y);
            float X2 = fmaf(dA, s_cB[2], xv.z);
            float X3 = fmaf(dA, s_cB[3], xv.w);
            float X4 = fmaf(dA, s_cB[4], x4v);

            float ss1 = fmaf(X0,X0, fmaf(X1,X1, fmaf(X2,X2, fmaf(X3,X3, X4*X4))));
            float r1  = rsqrtf(fmaf(0.2f, ss1, 1e-5f));
            float z0 = r1 * (X0*s_wf[0] + X1*s_wf[1] + X2*s_wf[2] + X3*s_wf[3] + X4*s_wf[4]);
            float z1 = r1 * (X0*s_wf[5] + X1*s_wf[6] + X2*s_wf[7] + X3*s_wf[8] + X4*s_wf[9]);
            float g0 = 0.5f*z0*(1.0f + erff(z0 * 0.70710678118654752f));
            float g1 = 0.5f*z1*(1.0f + erff(z1 * 0.70710678118654752f));
            float Y0 = X0 + g0*s_hp[0] + g1*s_hp[5];
            float Y1 = X1 + g0*s_hp[1] + g1*s_hp[6];
            float Y2 = X2 + g0*s_hp[2] + g1*s_hp[7];
            float Y3 = X3 + g0*s_hp[3] + g1*s_hp[8];
            float Y4 = X4 + g0*s_hp[4] + g1*s_hp[9];

            float ss2 = fmaf(Y0,Y0, fmaf(Y1,Y1, fmaf(Y2,Y2, fmaf(Y3,Y3, Y4*Y4))));
            float r2  = rsqrtf(fmaf(0.2f, ss2, 1e-5f));
            float u0 = r2 * (Y0*s_wh[0] + Y1*s_wh[1] + Y2*s_wh[2] + Y3*s_wh[3] + Y4*s_wh[4]);
            float u1 = r2 * (Y0*s_wh[5] + Y1*s_wh[6] + Y2*s_wh[7] + Y3*s_wh[8] + Y4*s_wh[9]);

            s_u[y * T_LEN + t] = make_float2(u0, u1);
        }
    }
    __syncthreads();

    // ---- staged, fully coalesced float4 output (block region 43520B contiguous) ----
    const long base_f  = base_tok * 10;
    const long total_f = total_tok * 10;
    float* __restrict__ ob = out + base_f;

    #pragma unroll
    for (int r = 0; r < 10; ++r) {
        const int f4 = tid + r * BTHREADS;       // 0..3167
        if (f4 < (SPB * T_LEN * 10) / 4) {
            const int el = f4 * 4;
            if (base_f + el + 4 <= total_f) {
                int tq = el / 10;
                int d  = el - tq * 10;
                float2 u = s_u[tq];
                float vv[4];
                #pragma unroll
                for (int k2 = 0; k2 < 4; ++k2) {
                    vv[k2] = fmaf(u.y, s_tt1[d], u.x * s_tt0[d]);
                    if (++d == 10) { d = 0; ++tq; u = s_u[tq]; }
                }
                reinterpret_cast<float4*>(ob)[f4] = make_float4(vv[0], vv[1], vv[2], vv[3]);
            }
        }
    }
}

extern "C" void kernel_launch(void* const* d_in, const int* in_sizes, int n_in,
                              void* d_out, int out_size)
{
    const int B = in_sizes[0] / T_LEN;
    const int grid = (B + SPB - 1) / SPB;
    micro_fused3<<<grid, BTHREADS>>>(
        (const int*)d_in[0],
        (const float*)d_in[1],
        (const float*)d_in[2],
        (const float*)d_in[3],
        (const float*)d_in[4],
        (const float*)d_in[5],
        (const float*)d_in[6],
        (const float*)d_in[7],
        (const float*)d_in[8],
        (const float*)d_in[9],
        (const float*)d_in[10],
        (const float*)d_in[11],
        (const float*)d_in[12],
        (float*)d_out, B);
}

// round 5
// speedup vs baseline: 2.2024x; 1.0430x over previous
#include <cuda_runtime.h>
#include <math.h>

#define SPB       64            // sequences per block (2 teams x 32)
#define T_LEN     34
#define NTAB      340
#define BTHREADS  256           // 8 warps = 2 teams of 4
#define JSTRIDE   35

__constant__ int c_flat[T_LEN] = {
    0,1,2,3,4,5,6,7,8,9, 11,
    0,1,2,3,4,5,6,7,8,9, 12,
    0,1,2,3,4,5,6,7,8,9, 10, 13
};

__device__ __forceinline__ float ex2f(float x) {
    float y;
    asm("ex2.approx.ftz.f32 %0, %1;" : "=f"(y) : "f"(x));
    return y;
}

// One attention pass: queries Qs (ascending). Iterate s once; query i expires at s==Qs[i].
// Writes raw (den, b) to urow[q].
template<int... Qs>
__device__ __forceinline__ void attn_pass(const int* __restrict__ jrow,
                                          const char* __restrict__ tab,
                                          const char* __restrict__ mtab,
                                          float2* __restrict__ urow)
{
    constexpr int N = sizeof...(Qs);
    const int qs[N] = {Qs...};
    float mx[N], my[N], mz[N], den[N], bb[N];
    #pragma unroll
    for (int i = 0; i < N; ++i) {
        const float4 m = *(const float4*)(mtab + jrow[qs[i]]);
        mx[i] = m.x; my[i] = m.y; mz[i] = m.z;
        den[i] = 0.f; bb[i] = 0.f;
    }
    int s = 0;
    #pragma unroll
    for (int seg = 0; seg < N; ++seg) {
        const int bound = qs[seg];
        for (; s <= bound; ++s) {
            const float4 kp = *(const float4*)(tab + jrow[s]);
            #pragma unroll
            for (int i = seg; i < N; ++i) {
                float d = fmaf(mx[i], kp.x, fmaf(my[i], kp.y, mz[i] * kp.z));
                float e = ex2f(d);
                den[i] += e;
                bb[i]   = fmaf(e, kp.w, bb[i]);
            }
        }
        urow[qs[seg]] = make_float2(den[seg], bb[seg]);
    }
}

__global__ __launch_bounds__(BTHREADS, 4)
void micro_fused5(
    const int*   __restrict__ idx,
    const float* __restrict__ tokA,
    const float* __restrict__ tokStart,
    const float* __restrict__ tokStride,
    const float* __restrict__ z_hi,
    const float* __restrict__ specialEq,
    const float* __restrict__ qW,         // (4,3)
    const float* __restrict__ phase,
    const float* __restrict__ outA,       // (5,)
    const float* __restrict__ outB,       // (5,)
    const float* __restrict__ nw,         // (5,)
    const float* __restrict__ fc1,        // (2,5)
    const float* __restrict__ hp,         // (2,5)
    float*       __restrict__ out,        // (B,34,10)
    int B)
{
    __shared__ float4 s_tab[NTAB];            // (h2,h3,h4, v')
    __shared__ float4 s_m  [NTAB];            // (m0,m1,m2, x4prenorm), m has 0.5*log2e baked
    __shared__ float4 s_x4 [NTAB];            // pre-norm (x0,x1,p0,p1)
    __shared__ int    s_j  [SPB * JSTRIDE];   // byte offset (s*10+c)*16
    __shared__ float2 s_u  [SPB * T_LEN + 1]; // (den,b) then in-place (u0,u1)
    __shared__ float  s_tt0[10], s_tt1[10];
    __shared__ float  s_cB[5], s_hp[10], s_wf[10], s_wh[10];

    const int  tid       = threadIdx.x;
    const long base_tok  = (long)blockIdx.x * (SPB * T_LEN);
    const long total_tok = (long)B * T_LEN;

    // ---- phase 1: coalesced idx load ----
    #pragma unroll
    for (int r = 0; r < 9; ++r) {
        int li = tid + r * BTHREADS;           // 0..2303
        if (li < SPB * T_LEN) {
            int  yy = li / T_LEN;
            int  ss = li - yy * T_LEN;
            long g  = base_tok + li;
            int  v  = (g < total_tok) ? idx[g] : 0;
            s_j[yy * JSTRIDE + ss] = (ss * 10 + v) << 4;
        }
    }
    if (tid < 5)  s_cB[tid] = outB[tid];
    if (tid < 10) {
        s_hp[tid] = hp[tid];
        int cc = tid % 5;
        s_wf[tid] = nw[cc] * fc1[tid];
        s_wh[tid] = nw[cc] * hp[tid];
    }

    // ---- phase 2: build 340-entry tables (fast-math trig; args tiny) ----
    #pragma unroll
    for (int r = 0; r < 2; ++r) {
        int i = tid + r * BTHREADS;
        if (i < NTAB) {
            const int tpos = i / 10;
            const int c    = i - tpos * 10;
            const int f    = c_flat[tpos];

            float p0, p1, p2;
            if (f < 10) {
                float a = 0.6283185307179586f * (float)f;
                p0 = 3.5f * __cosf(a);
                p1 = 3.5f * __sinf(a);
                p2 = 0.15f * (float)f;
            } else if (f == 10) {
                p0 = z_hi[0]; p1 = z_hi[1]; p2 = z_hi[2];
            } else if (f == 12) {
                p0 = specialEq[0]; p1 = specialEq[1]; p2 = specialEq[2];
            } else {
                p0 = p1 = p2 = 0.0f;
            }

            float ang = tokStart[0] + (float)c * tokStride[0];
            float amp = tokA[0];
            float x0 = amp * __cosf(ang);
            float x1 = amp * __sinf(ang);

            s_x4[i] = make_float4(x0, x1, p0, p1);
            if (tpos == 0) { s_tt0[c] = x0; s_tt1[c] = x1; }

            float ms = 0.2f * (x0*x0 + x1*x1 + p0*p0 + p1*p1 + p2*p2);
            float rr = rsqrtf(ms + 1e-5f);
            float h0 = x0 * rr * nw[0];
            float h1 = x1 * rr * nw[1];
            float h2 = p0 * rr * nw[2];
            float h3 = p1 * rr * nw[3];
            float h4 = p2 * rr * nw[4];

            float q0 = qW[0]*h2 + qW[1]*h3 + qW[2]*h4;
            float q1 = qW[3]*h2 + qW[4]*h3 + qW[5]*h4;
            float q2 = qW[6]*h2 + qW[7]*h3 + qW[8]*h4;
            float q3 = qW[9]*h2 + qW[10]*h3 + qW[11]*h4;

            float cp = __cosf(phase[0]);
            float sp = __sinf(phase[0]);
            float r0  = q0*cp - q1*sp;
            float r1v = q0*sp + q1*cp;
            float r2v = q2*cp - q3*sp;
            float r3  = q2*sp + q3*cp;
            const float LG = 0.5f * 1.4426950408889634f;
            float m0 = LG*(r0*qW[0] + r1v*qW[3] + r2v*qW[6] + r3*qW[9]);
            float m1 = LG*(r0*qW[1] + r1v*qW[4] + r2v*qW[7] + r3*qW[10]);
            float m2 = LG*(r0*qW[2] + r1v*qW[5] + r2v*qW[8] + r3*qW[11]);

            float w0s = hp[0]*outA[0] + hp[1]*outA[1] + hp[2]*outA[2] + hp[3]*outA[3] + hp[4]*outA[4];
            float w1s = hp[5]*outA[0] + hp[6]*outA[1] + hp[7]*outA[2] + hp[8]*outA[3] + hp[9]*outA[4];
            float vp  = h0*w0s + h1*w1s;

            s_tab[i] = make_float4(h2, h3, h4, vp);
            s_m[i]   = make_float4(m0, m1, m2, p2);
        }
    }
    __syncthreads();

    // ---- phase 3: attention (raw den/b into s_u) ----
    {
        const int y     = (tid & 31) + ((tid >> 7) << 5);   // lane + 32*team
        const int wtype = (tid >> 5) & 3;
        const int* __restrict__ jrow = s_j + y * JSTRIDE;
        const char* __restrict__ tab  = (const char*)s_tab;
        const char* __restrict__ mtab = (const char*)s_m;
        float2* __restrict__ urow = s_u + y * T_LEN;

        if (wtype == 0) {
            attn_pass<0,1,7,8,9,15,16>(jrow, tab, mtab, urow);
            attn_pass<23,24,33>       (jrow, tab, mtab, urow);
        } else if (wtype == 1) {
            attn_pass<6,14>           (jrow, tab, mtab, urow);
            attn_pass<17,22,25,28,32> (jrow, tab, mtab, urow);
        } else if (wtype == 2) {
            attn_pass<5,13>           (jrow, tab, mtab, urow);
            attn_pass<18,21,26,29,31> (jrow, tab, mtab, urow);
        } else {
            attn_pass<2,3,4,10,11,12> (jrow, tab, mtab, urow);
            attn_pass<19,20,27,30>    (jrow, tab, mtab, urow);
        }
    }
    __syncthreads();

    // ---- phase 4: uniform epilogue, in-place s_u: (den,b) -> (u0,u1) ----
    #pragma unroll
    for (int r = 0; r < 9; ++r) {
        int it = tid + r * BTHREADS;           // 0..2303
        if (it < SPB * T_LEN) {
            const int y = it / T_LEN;
            const int t = it - y * T_LEN;
            const float2 db = s_u[it];
            const float dA = __fdividef(db.y, db.x);
            const int jt = s_j[y * JSTRIDE + t];

            const float4 xv  = *(const float4*)((const char*)s_x4 + jt);
            const float  x4v = ((const float4*)((const char*)s_m + jt))->w;
            float X0 = fmaf(dA, s_cB[0], xv.x);
            float X1 = fmaf(dA, s_cB[1], xv.y);
            float X2 = fmaf(dA, s_cB[2], xv.z);
            float X3 = fmaf(dA, s_cB[3], xv.w);
            float X4 = fmaf(dA, s_cB[4], x4v);

            float ss1 = fmaf(X0,X0, fmaf(X1,X1, fmaf(X2,X2, fmaf(X3,X3, X4*X4))));
            float r1  = rsqrtf(fmaf(0.2f, ss1, 1e-5f));
            float z0 = r1 * (X0*s_wf[0] + X1*s_wf[1] + X2*s_wf[2] + X3*s_wf[3] + X4*s_wf[4]);
            float z1 = r1 * (X0*s_wf[5] + X1*s_wf[6] + X2*s_wf[7] + X3*s_wf[8] + X4*s_wf[9]);
            float g0 = 0.5f*z0*(1.0f + erff(z0 * 0.70710678118654752f));
            float g1 = 0.5f*z1*(1.0f + erff(z1 * 0.70710678118654752f));
            float Y0 = X0 + g0*s_hp[0] + g1*s_hp[5];
            float Y1 = X1 + g0*s_hp[1] + g1*s_hp[6];
            float Y2 = X2 + g0*s_hp[2] + g1*s_hp[7];
            float Y3 = X3 + g0*s_hp[3] + g1*s_hp[8];
            float Y4 = X4 + g0*s_hp[4] + g1*s_hp[9];

            float ss2 = fmaf(Y0,Y0, fmaf(Y1,Y1, fmaf(Y2,Y2, fmaf(Y3,Y3, Y4*Y4))));
            float r2  = rsqrtf(fmaf(0.2f, ss2, 1e-5f));
            float u0 = r2 * (Y0*s_wh[0] + Y1*s_wh[1] + Y2*s_wh[2] + Y3*s_wh[3] + Y4*s_wh[4]);
            float u1 = r2 * (Y0*s_wh[5] + Y1*s_wh[6] + Y2*s_wh[7] + Y3*s_wh[8] + Y4*s_wh[9]);

            s_u[it] = make_float2(u0, u1);
        }
    }
    __syncthreads();

    // ---- phase 5: coalesced float4 output ----
    const long base_f  = base_tok * 10;
    const long total_f = total_tok * 10;
    float* __restrict__ ob = out + base_f;
    const int nf4 = (SPB * T_LEN * 10) / 4;    // 5440

    for (int f4 = tid; f4 < nf4; f4 += BTHREADS) {
        const int el = f4 * 4;
        if (base_f + el + 4 <= total_f) {
            int tq = el / 10;
            int d  = el - tq * 10;
            float2 u = s_u[tq];
            float vv[4];
            #pragma unroll
            for (int k2 = 0; k2 < 4; ++k2) {
                vv[k2] = fmaf(u.y, s_tt1[d], u.x * s_tt0[d]);
                if (++d == 10) { d = 0; ++tq; u = s_u[tq]; }
            }
            reinterpret_cast<float4*>(ob)[f4] = make_float4(vv[0], vv[1], vv[2], vv[3]);
        }
    }
}

extern "C" void kernel_launch(void* const* d_in, const int* in_sizes, int n_in,
                              void* d_out, int out_size)
{
    const int B = in_sizes[0] / T_LEN;
    const int grid = (B + SPB - 1) / SPB;
    micro_fused5<<<grid, BTHREADS>>>(
        (const int*)d_in[0],
        (const float*)d_in[1],
        (const float*)d_in[2],
        (const float*)d_in[3],
        (const float*)d_in[4],
        (const float*)d_in[5],
        (const float*)d_in[6],
        (const float*)d_in[7],
        (const float*)d_in[8],
        (const float*)d_in[9],
        (const float*)d_in[10],
        (const float*)d_in[11],
        (const float*)d_in[12],
        (float*)d_out, B);
}